// round 8
// baseline (speedup 1.0000x reference)
#include <cuda_runtime.h>
#include <cuda.h>
#include <math.h>
#include <stdint.h>

#define IW 256
#define IH 256
#define HW (IW*IH)
#define NB 2
#define NC 96

// splat record: 48 channels + den + 3 pad = 52 floats (208 B, 16B-aligned)
#define REC 52
#define CHP 48               // channels per pass

__device__ __forceinline__ uint32_t f2tf32(float f){
    uint32_t r; asm("cvt.rna.tf32.f32 %0, %1;" : "=r"(r) : "f"(f)); return r;
}

// =============== tf32 mma.sync conv: NIC -> 64, 3x3 SAME, leaky 0.1 =========
// CTA tile: M=128 px, N=64 oc, K=NIC*9 in 32-chunks.
// Smem layout: row stride 40 words; K columns permuted so a fragment's
// (qc, qc+4) pair is adjacent (phys = k8*8 + (j&3)*2 + (j>>2)), then
// XOR-swizzled per row: col ^= ((row>>2)&7)<<1  -> conflict-free LDS.64.
#define AS_STRIDE 40
#define A_BUF (128*AS_STRIDE)
#define B_BUF (64*AS_STRIDE)

__device__ __forceinline__ int kphys(int k){          // k in 0..31
    int j = k & 7;
    return (k >> 3)*8 + ((j & 3) << 1) + (j >> 2);
}
__device__ __forceinline__ int rowxor(int row){       // even XOR value
    return ((row >> 2) & 7) << 1;
}

template<int NIC, bool HASM>
__global__ __launch_bounds__(256, 2)
void conv_mma_kernel(const float* __restrict__ metric,
                     const float* __restrict__ feat,
                     const float* __restrict__ wt,       // [64, NIC, 3, 3]
                     const float* __restrict__ bias,
                     float* __restrict__ out)            // [B,64,H,W]
{
    extern __shared__ float sm[];
    float* As = sm;                    // [2][A_BUF]
    float* Bs = sm + 2*A_BUF;          // [2][B_BUF]
    __shared__ float sbias[64];

    constexpr int KTOT = NIC*9;
    constexpr int NCH  = (KTOT + 31)/32;

    const int tid  = threadIdx.x;
    const int lane = tid & 31;
    const int warp = tid >> 5;
    const int wm = (warp >> 1) * 32;
    const int wn = (warp & 1) * 32;

    const int t  = blockIdx.x;
    const int b  = t >> 9;
    const int r  = t & 511;
    const int y0c = r >> 1;
    const int x0c = (r & 1) << 7;

    if (tid < 64) sbias[tid] = bias[tid];

    // staging coords: lanes along pixels (coalesced LDG for A)
    const int am_  = tid & 127;          // pixel within tile
    const int kh_  = tid >> 7;           // 0/1: handles k = kh+2i
    const int axor = rowxor(am_);

    float acc[2][4][4];
    #pragma unroll
    for (int i = 0; i < 2; ++i)
        #pragma unroll
        for (int j = 0; j < 4; ++j)
            #pragma unroll
            for (int k = 0; k < 4; ++k) acc[i][j][k] = 0.f;

    float areg[16], breg[8];

    auto load_chunk = [&](int ch) {
        // A: 128 px x 32 k  (im2col on the fly; lanes -> consecutive x)
        #pragma unroll
        for (int i = 0; i < 16; ++i) {
            int kk   = ch*32 + kh_ + 2*i;
            int ic   = kk / 9;
            int tap  = kk - ic*9;
            int ty   = tap / 3;
            int tx   = tap - ty*3;
            int x = x0c + am_ + tx - 1;
            int y = y0c + ty - 1;
            float v = 0.f;
            if (ic < NIC && (unsigned)x < IW && (unsigned)y < IH) {
                const float* src;
                if (HASM) src = (ic == 0) ? (metric + (size_t)b*HW)
                                          : (feat + ((size_t)b*(NIC-1) + (ic-1))*HW);
                else      src = feat + ((size_t)b*NIC + ic)*HW;
                v = __ldg(src + y*IW + x);
            }
            areg[i] = v;
        }
        // B: 64 oc x 32 k (lanes -> consecutive k: coalesced)
        #pragma unroll
        for (int i = 0; i < 8; ++i) {
            int e    = tid + i*256;
            int oc   = e >> 5;
            int kk32 = e & 31;
            int kk   = ch*32 + kk32;
            breg[i] = (kk < KTOT) ? __ldg(wt + (size_t)oc*KTOT + kk) : 0.f;
        }
    };
    auto store_chunk = [&](int buf) {
        float* ab = As + buf*A_BUF;
        float* bb = Bs + buf*B_BUF;
        #pragma unroll
        for (int i = 0; i < 16; ++i) {
            int k = kh_ + 2*i;
            int col = kphys(k) ^ axor;
            ab[am_*AS_STRIDE + col] = __uint_as_float(f2tf32(areg[i]));
        }
        #pragma unroll
        for (int i = 0; i < 8; ++i) {
            int e = tid + i*256;
            int oc = e >> 5, kk32 = e & 31;
            int col = kphys(kk32) ^ rowxor(oc);
            bb[oc*AS_STRIDE + col] = __uint_as_float(f2tf32(breg[i]));
        }
    };

    load_chunk(0);

    const int qr = lane >> 2;
    const int qc = lane & 3;

    for (int s = 0; s < NCH; ++s) {
        const int buf = s & 1;
        store_chunk(buf);
        __syncthreads();
        if (s + 1 < NCH) load_chunk(s + 1);

        const float* ab = As + buf*A_BUF;
        const float* bb = Bs + buf*B_BUF;

        #pragma unroll
        for (int k8 = 0; k8 < 4; ++k8) {
            const int cb = k8*8 + 2*qc;    // physical column pair base (pre-XOR)
            // A fragments: 2 m16 atoms, rows (qr, qr+8) -> 2 LDS.64 each
            uint32_t afr[2][4];
            #pragma unroll
            for (int am = 0; am < 2; ++am) {
                int r0 = wm + am*16 + qr;
                int r1 = r0 + 8;
                float2 lo = *reinterpret_cast<const float2*>(ab + r0*AS_STRIDE + (cb ^ rowxor(r0)));
                float2 hi = *reinterpret_cast<const float2*>(ab + r1*AS_STRIDE + (cb ^ rowxor(r1)));
                afr[am][0] = __float_as_uint(lo.x);
                afr[am][1] = __float_as_uint(hi.x);
                afr[am][2] = __float_as_uint(lo.y);
                afr[am][3] = __float_as_uint(hi.y);
            }
            // B fragments: 4 n8 atoms -> 1 LDS.64 each
            uint32_t bfr[4][2];
            #pragma unroll
            for (int j = 0; j < 4; ++j) {
                int rb = wn + j*8 + qr;
                float2 v = *reinterpret_cast<const float2*>(bb + rb*AS_STRIDE + (cb ^ rowxor(rb)));
                bfr[j][0] = __float_as_uint(v.x);
                bfr[j][1] = __float_as_uint(v.y);
            }
            #pragma unroll
            for (int am = 0; am < 2; ++am)
                #pragma unroll
                for (int j = 0; j < 4; ++j)
                    asm volatile(
                        "mma.sync.aligned.m16n8k8.row.col.f32.tf32.tf32.f32 "
                        "{%0,%1,%2,%3}, {%4,%5,%6,%7}, {%8,%9}, {%0,%1,%2,%3};"
                        : "+f"(acc[am][j][0]), "+f"(acc[am][j][1]),
                          "+f"(acc[am][j][2]), "+f"(acc[am][j][3])
                        : "r"(afr[am][0]), "r"(afr[am][1]), "r"(afr[am][2]), "r"(afr[am][3]),
                          "r"(bfr[j][0]), "r"(bfr[j][1]));
        }
        __syncthreads();
    }

    // ---- epilogue ----
    #pragma unroll
    for (int am = 0; am < 2; ++am) {
        #pragma unroll
        for (int j = 0; j < 4; ++j) {
            #pragma unroll
            for (int h = 0; h < 2; ++h) {
                int m  = wm + am*16 + qr + h*8;
                #pragma unroll
                for (int cc = 0; cc < 2; ++cc) {
                    int oc = wn + j*8 + qc*2 + cc;
                    float v = acc[am][j][h*2 + cc] + sbias[oc];
                    v = v > 0.f ? v : 0.1f * v;
                    out[(((size_t)b*64 + oc)*IH + y0c)*IW + x0c + m] = v;
                }
            }
        }
    }
}

// ======================= 1. backwarp + mean |diff| =========================
__global__ void warp_diff_kernel(const float* __restrict__ A,
                                 const float* __restrict__ Bf,
                                 const float* __restrict__ bi_flow,
                                 int flow_ch, float* __restrict__ mout)
{
    int idx = blockIdx.x * blockDim.x + threadIdx.x;
    if (idx >= NB*HW) return;
    int b = idx / HW;
    int p = idx - b*HW;
    int y = p / IW, x = p - y*IW;

    const float* fl = bi_flow + (b*4 + flow_ch) * HW;
    float tx = (float)x + fl[p]      * 0.125f;
    float ty = (float)y + fl[HW + p] * 0.125f;
    float x0f = floorf(tx), y0f = floorf(ty);
    float fx = tx - x0f, fy = ty - y0f;
    int x0 = (int)x0f, y0 = (int)y0f;
    int x1 = x0 + 1,  y1 = y0 + 1;

    bool vx0 = (x0 >= 0) & (x0 < IW), vx1 = (x1 >= 0) & (x1 < IW);
    bool vy0 = (y0 >= 0) & (y0 < IH), vy1 = (y1 >= 0) & (y1 < IH);
    bool v00 = vx0 & vy0, v10 = vx1 & vy0, v01 = vx0 & vy1, v11 = vx1 & vy1;
    float w00 = (1.f-fx)*(1.f-fy), w10 = fx*(1.f-fy);
    float w01 = (1.f-fx)*fy,       w11 = fx*fy;
    int o00 = v00 ? (y0*IW + x0) : 0;
    int o10 = v10 ? (y0*IW + x1) : 0;
    int o01 = v01 ? (y1*IW + x0) : 0;
    int o11 = v11 ? (y1*IW + x1) : 0;

    const float* Ab = A  + b*NC*HW + p;
    const float* Bb = Bf + b*NC*HW;
    float acc = 0.f;
    #pragma unroll 4
    for (int c = 0; c < NC; ++c) {
        const float* Bc = Bb + c*HW;
        float wv = 0.f;
        if (v00) wv += w00 * Bc[o00];
        if (v10) wv += w10 * Bc[o10];
        if (v01) wv += w01 * Bc[o01];
        if (v11) wv += w11 * Bc[o11];
        acc += fabsf(Ab[c*HW] - wv);
    }
    mout[idx] = acc * (1.f/96.f);
}

// conv3: 64 -> 1, then emet = exp(clip(alpha * (conv+b), -20, 20))
__global__ __launch_bounds__(256)
void conv3_kernel(const float* __restrict__ x,
                  const float* __restrict__ wt,   // [1,64,3,3]
                  const float* __restrict__ bias,
                  const float* __restrict__ alpha,
                  float* __restrict__ emet)       // [B,H,W]
{
    __shared__ float sp[10*34];
    __shared__ float sw[9];
    int tid = threadIdx.x;
    int x0 = blockIdx.x * 32;
    int y0 = blockIdx.y * 8;
    int b  = blockIdx.z;
    int xx = tid & 31, yy = tid >> 5;

    float acc = 0.f;
    for (int ic = 0; ic < 64; ++ic) {
        const float* src = x + (b*64 + ic)*HW;
        for (int i = tid; i < 10*34; i += 256) {
            int r = i / 34, c = i - r*34;
            int gy = y0 - 1 + r, gx = x0 - 1 + c;
            sp[i] = (gy >= 0 && gy < IH && gx >= 0 && gx < IW) ? src[gy*IW + gx] : 0.f;
        }
        if (tid < 9) sw[tid] = wt[ic*9 + tid];
        __syncthreads();
        #pragma unroll
        for (int ky = 0; ky < 3; ++ky)
            #pragma unroll
            for (int kx = 0; kx < 3; ++kx)
                acc = fmaf(sw[ky*3 + kx], sp[(yy + ky)*34 + xx + kx], acc);
        __syncthreads();
    }
    float v = acc + bias[0];
    v = alpha[0] * v;
    v = fminf(fmaxf(v, -20.f), 20.f);
    emet[b*HW + (y0 + yy)*IW + x0 + xx] = __expf(v);
}

// ======================= 3. softsplat (48-ch record passes) =================
__global__ void splat48_kernel(const float* __restrict__ feat,
                               const float* __restrict__ bi_flow,
                               int flow_ch, int c0,
                               const float* __restrict__ emet,   // [B,H,W]
                               float* __restrict__ accum)
{
    int idx = blockIdx.x * blockDim.x + threadIdx.x;
    if (idx >= NB*HW) return;
    int b = idx / HW;
    int p = idx - b*HW;
    int y = p / IW, x = p - y*IW;

    const float* fl = bi_flow + (b*4 + flow_ch)*HW;
    float tx = (float)x + fl[p]      * 0.125f;
    float ty = (float)y + fl[HW + p] * 0.125f;
    float x0f = floorf(tx), y0f = floorf(ty);
    float fx = tx - x0f, fy = ty - y0f;
    int x0 = (int)x0f, y0 = (int)y0f;
    int x1 = x0 + 1,  y1 = y0 + 1;
    bool vx0 = (x0 >= 0) & (x0 < IW), vx1 = (x1 >= 0) & (x1 < IW);
    bool vy0 = (y0 >= 0) & (y0 < IH), vy1 = (y1 >= 0) & (y1 < IH);
    bool v00 = vx0 & vy0, v10 = vx1 & vy0, v01 = vx0 & vy1, v11 = vx1 & vy1;
    float w00 = (1.f-fx)*(1.f-fy), w10 = fx*(1.f-fy);
    float w01 = (1.f-fx)*fy,       w11 = fx*fy;
    int t00 = y0*IW + x0, t10 = y0*IW + x1;
    int t01 = y1*IW + x0, t11 = y1*IW + x1;

    float m = emet[idx];

    float vals[CHP];
    const float* fb = feat + ((size_t)b*NC + c0)*HW + p;
    #pragma unroll
    for (int c = 0; c < CHP; ++c) vals[c] = fb[(size_t)c*HW] * m;

    float* ab = accum + (size_t)b*HW*REC;

    #define DO_CORNER(valid, tgt, w) do {                                     \
        if (valid) {                                                          \
            float* base = ab + (size_t)(tgt)*REC;                             \
            float wv = (w);                                                   \
            _Pragma("unroll")                                                 \
            for (int k = 0; k < CHP/4; ++k) {                                 \
                asm volatile("red.global.add.v4.f32 [%0], {%1,%2,%3,%4};"     \
                    :: "l"(base + 4*k),                                       \
                       "f"(vals[4*k+0]*wv), "f"(vals[4*k+1]*wv),              \
                       "f"(vals[4*k+2]*wv), "f"(vals[4*k+3]*wv)               \
                    : "memory");                                              \
            }                                                                 \
            atomicAdd(base + CHP, m*wv);                                      \
        }                                                                     \
    } while(0)

    DO_CORNER(v00, t00, w00);
    DO_CORNER(v10, t10, w10);
    DO_CORNER(v01, t01, w01);
    DO_CORNER(v11, t11, w11);
    #undef DO_CORNER
}

// Transposing normalize: records -> out[B, c0..c0+47, H, W]
__global__ __launch_bounds__(256)
void normalize48_kernel(const float* __restrict__ accum,
                        int c0,
                        float* __restrict__ out)   // [B,96,H,W] base
{
    __shared__ float s[32*53];
    const int tid = threadIdx.x;
    const int pbase = blockIdx.x * 32;
    const int b = pbase / HW;
    const int prow = pbase - b*HW;

    const float4* a4 = reinterpret_cast<const float4*>(accum);
    #pragma unroll
    for (int it = 0; it < 2; ++it) {
        int i = tid + it*256;
        if (i < 32*13) {
            int px = i / 13, k = i - px*13;
            float4 v = a4[(size_t)(pbase + px)*13 + k];
            float* d = s + px*53 + 4*k;
            d[0] = v.x; d[1] = v.y; d[2] = v.z; d[3] = v.w;
        }
    }
    __syncthreads();

    #pragma unroll
    for (int it = 0; it < 6; ++it) {
        int i = tid + it*256;
        int c  = i >> 5;
        int px = i & 31;
        float num = s[px*53 + c];
        float den = s[px*53 + CHP];
        out[((size_t)b*NC + c0 + c)*HW + prow + px] = num / (den + 1e-7f);
    }
}

// ======================= 4. correlation ====================================
__global__ __launch_bounds__(256, 1)
void corr_kernel(const float* __restrict__ wl,
                 const float* __restrict__ wr,
                 float* __restrict__ cost)
{
    __shared__ float sa[8*32];
    __shared__ float sb[16*40];
    int tid = threadIdx.x;
    int x0 = blockIdx.x * 32;
    int y0 = blockIdx.y * 8;
    int b  = blockIdx.z;
    int xx = tid & 31, yy = tid >> 5;

    float acc[81];
    #pragma unroll
    for (int d = 0; d < 81; ++d) acc[d] = 0.f;

    for (int c = 0; c < NC; ++c) {
        const float* lsrc = wl + (b*NC + c)*HW;
        const float* rsrc = wr + (b*NC + c)*HW;
        sa[tid] = lsrc[(y0 + yy)*IW + x0 + xx];
        for (int i = tid; i < 16*40; i += 256) {
            int r = i / 40, col = i - r*40;
            int gy = y0 - 4 + r, gx = x0 - 4 + col;
            sb[i] = (gy >= 0 && gy < IH && gx >= 0 && gx < IW) ? rsrc[gy*IW + gx] : 0.f;
        }
        __syncthreads();
        float a = sa[tid];
        #pragma unroll
        for (int dy = 0; dy < 9; ++dy)
            #pragma unroll
            for (int dx = 0; dx < 9; ++dx)
                acc[dy*9 + dx] = fmaf(a, sb[(yy + dy)*40 + xx + dx], acc[dy*9 + dx]);
        __syncthreads();
    }
    #pragma unroll
    for (int d = 0; d < 81; ++d) {
        float v = acc[d] * (1.f/96.f);
        v = v > 0.f ? v : 0.1f * v;
        cost[((b*81 + d)*IH + y0 + yy)*IW + x0 + xx] = v;
    }
}

// ======================= launch ============================================
extern "C" void kernel_launch(void* const* d_in, const int* in_sizes, int n_in,
                              void* d_out, int out_size)
{
    const float* bi_flow = (const float*)d_in[0];
    const float* fL      = (const float*)d_in[1];
    const float* fR      = (const float*)d_in[2];
    const float* alpha   = (const float*)d_in[3];
    const float* w1 = (const float*)d_in[4];
    const float* b1 = (const float*)d_in[5];
    const float* w2 = (const float*)d_in[6];
    const float* b2 = (const float*)d_in[7];
    const float* w3 = (const float*)d_in[8];
    const float* b3 = (const float*)d_in[9];

    float* out  = (float*)d_out;
    float* wL   = out;
    float* wR   = out + (size_t)NB*NC*HW;
    float* cost = out + (size_t)2*NB*NC*HW;

    float* s_accum = cost;
    float* s_tail  = cost + 10616832 - 4*131072;
    float* s_mL    = s_tail;
    float* s_mR    = s_tail + 131072;
    float* s_emetL = s_tail + 262144;
    float* s_emetR = s_tail + 393216;
    float* s_x1 = wL;
    float* s_x2 = wR;

    const int SMEM_CONV = (2*A_BUF + 2*B_BUF) * sizeof(float);   // 61440 B
    cudaFuncSetAttribute(conv_mma_kernel<97, true>,
                         cudaFuncAttributeMaxDynamicSharedMemorySize, SMEM_CONV);
    cudaFuncSetAttribute(conv_mma_kernel<64, false>,
                         cudaFuncAttributeMaxDynamicSharedMemorySize, SMEM_CONV);

    const int NPIX = NB*HW;
    const size_t ACCUM_BYTES = (size_t)NB*HW*REC*sizeof(float);
    dim3 grid3(IW/32, IH/8, NB);
    const int CTILES = NB*512;
    const int NORMB = NPIX/32;

    // ---- metrics ----
    warp_diff_kernel<<<(NPIX+255)/256, 256>>>(fL, fR, bi_flow, 0, s_mL);
    warp_diff_kernel<<<(NPIX+255)/256, 256>>>(fR, fL, bi_flow, 2, s_mR);

    // ---- metric_net L ----
    conv_mma_kernel<97, true><<<CTILES, 256, SMEM_CONV>>>(s_mL, fL, w1, b1, s_x1);
    conv_mma_kernel<64, false><<<CTILES, 256, SMEM_CONV>>>(nullptr, s_x1, w2, b2, s_x2);
    conv3_kernel<<<grid3, 256>>>(s_x2, w3, b3, alpha, s_emetL);

    // ---- metric_net R ----
    conv_mma_kernel<97, true><<<CTILES, 256, SMEM_CONV>>>(s_mR, fR, w1, b1, s_x1);
    conv_mma_kernel<64, false><<<CTILES, 256, SMEM_CONV>>>(nullptr, s_x1, w2, b2, s_x2);
    conv3_kernel<<<grid3, 256>>>(s_x2, w3, b3, alpha, s_emetR);

    // ---- softsplat L ----
    for (int c0 = 0; c0 < NC; c0 += CHP) {
        cudaMemsetAsync(s_accum, 0, ACCUM_BYTES);
        splat48_kernel<<<(NPIX+255)/256, 256>>>(fL, bi_flow, 0, c0, s_emetL, s_accum);
        normalize48_kernel<<<NORMB, 256>>>(s_accum, c0, wL);
    }

    // ---- softsplat R ----
    for (int c0 = 0; c0 < NC; c0 += CHP) {
        cudaMemsetAsync(s_accum, 0, ACCUM_BYTES);
        splat48_kernel<<<(NPIX+255)/256, 256>>>(fR, bi_flow, 2, c0, s_emetR, s_accum);
        normalize48_kernel<<<NORMB, 256>>>(s_accum, c0, wR);
    }

    // ---- correlation ----
    corr_kernel<<<grid3, 256>>>(wL, wR, cost);
}